// round 10
// baseline (speedup 1.0000x reference)
#include <cuda_runtime.h>
#include <cuda_bf16.h>
#include <cstdint>

// Problem constants
#define B_    64
#define N_    128
#define LVLS  3
#define NT    32
#define TL    32
#define H_    256
#define OUT_  10
#define BC    4              // batch chunks
#define MB    16             // batch rows per chunk
#define NJOBS (LVLS*NT*BC)   // 384

// Device-global scratch (allocation-free)
__device__ float  g_v[LVLS * 1024];
__device__ float  g_u[LVLS * 1024];
__device__ float4 g_Wt4[LVLS * 64 * 1024];   // [l][k4][row] = W_hh[l][row][4k4..+3]
__device__ float  g_partial[NJOBS * MB * OUT_];
__device__ int    g_order[NJOBS];
__device__ int    g_ticket;

// ---- packed f32x2 helpers (sm_100+) --------------------------------------
__device__ __forceinline__ unsigned long long pack2(float lo, float hi) {
    unsigned long long r;
    asm("mov.b64 %0, {%1, %2};" : "=l"(r) : "f"(lo), "f"(hi));
    return r;
}
__device__ __forceinline__ void unpack2(unsigned long long v, float& lo, float& hi) {
    asm("mov.b64 {%0, %1}, %2;" : "=f"(lo), "=f"(hi) : "l"(v));
}
__device__ __forceinline__ unsigned long long ffma2(unsigned long long a,
                                                    unsigned long long b,
                                                    unsigned long long c) {
    unsigned long long d;
    asm("fma.rn.f32x2 %0, %1, %2, %3;" : "=l"(d) : "l"(a), "l"(b), "l"(c));
    return d;
}

__device__ __forceinline__ float fast_sig(float x) {
    return __fdividef(1.0f, 1.0f + __expf(-x));
}
__device__ __forceinline__ float fast_tanh(float x) {
    float s = __fdividef(1.0f, 1.0f + __expf(-2.0f * x));
    return fmaf(2.0f, s, -1.0f);
}

// ---------------------------------------------------------------------------
// prep: v = W_ih@w_enc, u = W_ih@b_enc + b_ih + b_hh; transpose W_hh into
// g_Wt4 (coalesced-by-row layout). One thread per global gate row (3072).
// ---------------------------------------------------------------------------
__global__ void prep_kernel(const float* __restrict__ W_ih,
                            const float* __restrict__ W_enc,
                            const float* __restrict__ b_enc,
                            const float* __restrict__ b_ih,
                            const float* __restrict__ b_hh,
                            const float* __restrict__ W_hh) {
    __shared__ float we[H_];
    __shared__ float be[H_];
    int tid = threadIdx.x;
    we[tid] = W_enc[tid];
    be[tid] = b_enc[tid];
    __syncthreads();

    int r   = blockIdx.x * 256 + tid;   // 0..3071
    int l   = r >> 10;
    int row = r & 1023;
    const float4* Wr = reinterpret_cast<const float4*>(W_ih + (size_t)r * H_);
    const float4* Hr = reinterpret_cast<const float4*>(W_hh + (size_t)r * H_);
    float4* dst = g_Wt4 + (((size_t)l) << 16) + row;

    float sv = 0.f, su = 0.f;
#pragma unroll 4
    for (int k4 = 0; k4 < 64; k4++) {
        float4 w = __ldg(Wr + k4);
        int k = 4 * k4;
        sv = fmaf(w.x, we[k + 0], sv); sv = fmaf(w.y, we[k + 1], sv);
        sv = fmaf(w.z, we[k + 2], sv); sv = fmaf(w.w, we[k + 3], sv);
        su = fmaf(w.x, be[k + 0], su); su = fmaf(w.y, be[k + 1], su);
        su = fmaf(w.z, be[k + 2], su); su = fmaf(w.w, be[k + 3], su);
        dst[k4 << 10] = __ldg(Hr + k4);
    }
    g_v[r] = sv;
    g_u[r] = su + b_ih[r] + b_hh[r];
}

// ---------------------------------------------------------------------------
// order: rank jobs by descending trunk length (LPT) + ticket reset.
// ---------------------------------------------------------------------------
__global__ void order_kernel(const int* __restrict__ trunk_len) {
    __shared__ int len_s[NJOBS];
    int i = threadIdx.x;               // 0..383
    int l = i >> 7;
    int t = (i >> 2) & 31;
    int L = trunk_len[l * NT + t];
    L = min(max(L, 1), TL);
    len_s[i] = L;
    __syncthreads();
    int Li = len_s[i];
    int rank = 0;
    for (int k = 0; k < NJOBS; k++) {
        int Lk = len_s[k];
        rank += (Lk > Li) || (Lk == Li && k < i);
    }
    g_order[rank] = i;
    if (i == 0) g_ticket = 0;
}

// ---------------------------------------------------------------------------
// Main LSTM: 512-thread persistent CTAs, LPT ticket dispatch.
// k-paired FFMA2 (zero packing MOVs in the hot loop) + sync-every-8-k4
// cadence so the two batch-halves' duplicate W reads stay inside a 128 KB
// L1 window. Thread (j=tid&255, hh=tid>>8) owns gate rows
// {j,j+256,j+512,j+768} for batch rows [8hh, 8hh+8).
// ---------------------------------------------------------------------------
__global__ void __launch_bounds__(512, 1)
lstm_kernel(const float* __restrict__ bf,
            const int*   __restrict__ trunk_idx,
            const int*   __restrict__ trunk_len,
            const float* __restrict__ W_lin) {
    const int tid = threadIdx.x;
    const int j   = tid & 255;
    const int hh  = tid >> 8;          // batch half: rows [8hh, 8hh+8)

    __shared__ float hs[MB][H_];       // hidden state (16 KB)
    __shared__ float sbf[MB][N_];      // batch_feature rows (8 KB)
    __shared__ int   idx_s[TL];
    __shared__ int   job_s;
    __shared__ int   len_s;

    for (;;) {
        if (tid == 0) {
            int tk = atomicAdd(&g_ticket, 1);
            job_s = (tk < NJOBS) ? g_order[tk] : -1;
        }
        __syncthreads();
        const int job = job_s;
        if (job < 0) break;

        const int l  = job >> 7;
        const int t  = (job >> 2) & 31;
        const int bc = job & 3;

        float vj[4], uj[4];
#pragma unroll
        for (int g = 0; g < 4; g++) {
            vj[g] = g_v[l * 1024 + (g << 8) + j];
            uj[g] = g_u[l * 1024 + (g << 8) + j];
        }
        for (int i = tid; i < MB * N_; i += 512)
            sbf[i >> 7][i & 127] = bf[(bc * MB + (i >> 7)) * N_ + (i & 127)];
        if (tid < TL) idx_s[tid] = trunk_idx[(l * NT + t) * TL + tid];
        if (tid == 0) {
            int L = trunk_len[l * NT + t];
            len_s = min(max(L, 1), TL);
        }
        for (int i = tid; i < MB * H_; i += 512)
            hs[i >> 8][i & 255] = 0.f;
        __syncthreads();

        const int len = len_s;
        float c[8];
#pragma unroll
        for (int m = 0; m < 8; m++) c[m] = 0.f;

        const float4* Wk = g_Wt4 + (((size_t)l) << 16) + j;  // + (k4<<10) + g*256

        for (int step = 0; step < len; step++) {
            const int n = idx_s[step];

            // acc[g][m]: f32x2 = (even-k partial, odd-k partial).
            unsigned long long acc[4][8];
#pragma unroll
            for (int m = 0; m < 8; m++) {
                float s = sbf[8 * hh + m][n];
#pragma unroll
                for (int g = 0; g < 4; g++)
                    acc[g][m] = pack2(fmaf(s, vj[g], uj[g]), 0.f);
            }

            // Recurrent GEMM: 8 groups of 8 k4 with re-convergence barriers
            // (128 KB W window per group -> both halves hit L1 on the dup).
#pragma unroll 1
            for (int k8 = 0; k8 < 8; k8++) {
#pragma unroll 2
                for (int kk = 0; kk < 8; kk++) {
                    const int k4 = k8 * 8 + kk;
                    const float4* Wb = Wk + (k4 << 10);
                    const float4 w0 = __ldg(Wb);
                    const float4 w1 = __ldg(Wb + 256);
                    const float4 w2 = __ldg(Wb + 512);
                    const float4 w3 = __ldg(Wb + 768);
                    const ulonglong2 W0 = *reinterpret_cast<const ulonglong2*>(&w0);
                    const ulonglong2 W1 = *reinterpret_cast<const ulonglong2*>(&w1);
                    const ulonglong2 W2 = *reinterpret_cast<const ulonglong2*>(&w2);
                    const ulonglong2 W3 = *reinterpret_cast<const ulonglong2*>(&w3);
#pragma unroll
                    for (int m = 0; m < 8; m++) {
                        const ulonglong2 hq = *reinterpret_cast<const ulonglong2*>(
                            &hs[8 * hh + m][k4 * 4]);          // one broadcast LDS.128
                        acc[0][m] = ffma2(hq.x, W0.x, acc[0][m]);
                        acc[0][m] = ffma2(hq.y, W0.y, acc[0][m]);
                        acc[1][m] = ffma2(hq.x, W1.x, acc[1][m]);
                        acc[1][m] = ffma2(hq.y, W1.y, acc[1][m]);
                        acc[2][m] = ffma2(hq.x, W2.x, acc[2][m]);
                        acc[2][m] = ffma2(hq.y, W2.y, acc[2][m]);
                        acc[3][m] = ffma2(hq.x, W3.x, acc[3][m]);
                        acc[3][m] = ffma2(hq.y, W3.y, acc[3][m]);
                    }
                }
                __syncthreads();   // re-converge halves; final guards hs overwrite
            }

            // Activations: gate = lane0 + lane1 of each f32x2 partial pair.
#pragma unroll
            for (int m = 0; m < 8; m++) {
                float i0, i1, f0, f1, g0, g1, o0, o1;
                unpack2(acc[0][m], i0, i1);
                unpack2(acc[1][m], f0, f1);
                unpack2(acc[2][m], g0, g1);
                unpack2(acc[3][m], o0, o1);
                float gi = i0 + i1, gf = f0 + f1, gg = g0 + g1, go = o0 + o1;
                float cm = fmaf(fast_sig(gf), c[m], fast_sig(gi) * fast_tanh(gg));
                c[m] = cm;
                hs[8 * hh + m][j] = fast_sig(go) * fast_tanh(cm);
            }
            __syncthreads();   // hs complete before next step's reads
        }

        // ---- epilogue: partial[m][o] = h_last[m] @ W_lin[l][:,o] ----
        if (hh == 0 && j < MB * OUT_) {
            int m = j / OUT_;
            int o = j - m * OUT_;
            const float* Wl = W_lin + (size_t)l * H_ * OUT_ + o;
            float s = 0.f;
#pragma unroll 8
            for (int d = 0; d < H_; d++)
                s = fmaf(hs[m][d], __ldg(Wl + d * OUT_), s);
            g_partial[(job * MB + m) * OUT_ + o] = s;
        }
        __syncthreads();   // protect shared state before next job
    }
}

// ---------------------------------------------------------------------------
// Deterministic final reduction over trunks and levels (+ b_lin per level).
// ---------------------------------------------------------------------------
__global__ void reduce_kernel(const float* __restrict__ b_lin,
                              float* __restrict__ out) {
    int i = blockIdx.x * blockDim.x + threadIdx.x;
    if (i >= B_ * OUT_) return;
    int b  = i / OUT_;
    int o  = i % OUT_;
    int bc = b / MB;
    int m  = b % MB;
    float s = 0.f;
#pragma unroll
    for (int l = 0; l < LVLS; l++) {
        s += b_lin[l * OUT_ + o];
        for (int t = 0; t < NT; t++) {
            int job = (l * NT + t) * BC + bc;
            s += g_partial[(job * MB + m) * OUT_ + o];
        }
    }
    out[i] = s;
}

// ---------------------------------------------------------------------------
extern "C" void kernel_launch(void* const* d_in, const int* in_sizes, int n_in,
                              void* d_out, int out_size) {
    const float* batch_feature = (const float*)d_in[0];
    const int*   trunk_idx     = (const int*)  d_in[1];
    const int*   trunk_len     = (const int*)  d_in[2];
    const float* W_enc         = (const float*)d_in[3];
    const float* b_enc         = (const float*)d_in[4];
    const float* W_ih          = (const float*)d_in[5];
    const float* W_hh          = (const float*)d_in[6];
    const float* b_ih          = (const float*)d_in[7];
    const float* b_hh          = (const float*)d_in[8];
    const float* W_lin         = (const float*)d_in[9];
    const float* b_lin         = (const float*)d_in[10];
    float* out = (float*)d_out;

    prep_kernel<<<12, 256>>>(W_ih, W_enc, b_enc, b_ih, b_hh, W_hh);
    order_kernel<<<1, NJOBS>>>(trunk_len);
    lstm_kernel<<<NJOBS, 512>>>(batch_feature, trunk_idx, trunk_len, W_lin);
    reduce_kernel<<<(B_ * OUT_ + 127) / 128, 128>>>(b_lin, out);
}

// round 11
// speedup vs baseline: 1.3465x; 1.3465x over previous
#include <cuda_runtime.h>
#include <cuda_bf16.h>
#include <cstdint>

// Problem constants
#define B_    64
#define N_    128
#define LVLS  3
#define NT    32
#define TL    32
#define H_    256
#define OUT_  10
#define BC    4              // batch chunks
#define MB    16             // batch rows per chunk
#define NJOBS (LVLS*NT*BC)   // 384

// Dynamic smem layout (bytes)
#define SM_HP   0                         // float2 hp[8][256]   = 16384
#define SM_SBF  16384                     // float2 sbf2[8][128] =  8192
#define SM_EX   24576                     // float2 ex[2][2][4][256] = 32768
#define SM_IDX  57344                     // int idx_s[TL]
#define SM_MISC 57472                     // int misc[2] : job, len
#define SM_SZ   57600

// Device-global scratch (allocation-free)
__device__ float  g_v[LVLS * 1024];
__device__ float  g_u[LVLS * 1024];
__device__ float4 g_Wt4[LVLS * 64 * 1024];   // [l][k4][row] = W_hh[l][row][4k4..+3]
__device__ float  g_partial[NJOBS * MB * OUT_];
__device__ int    g_order[NJOBS];
__device__ int    g_ticket;

// ---- packed f32x2 helpers (sm_100+) --------------------------------------
__device__ __forceinline__ unsigned long long pack2(float lo, float hi) {
    unsigned long long r;
    asm("mov.b64 %0, {%1, %2};" : "=l"(r) : "f"(lo), "f"(hi));
    return r;
}
__device__ __forceinline__ void unpack2(unsigned long long v, float& lo, float& hi) {
    asm("mov.b64 {%0, %1}, %2;" : "=f"(lo), "=f"(hi) : "l"(v));
}
__device__ __forceinline__ unsigned long long ffma2(unsigned long long a,
                                                    unsigned long long b,
                                                    unsigned long long c) {
    unsigned long long d;
    asm("fma.rn.f32x2 %0, %1, %2, %3;" : "=l"(d) : "l"(a), "l"(b), "l"(c));
    return d;
}

__device__ __forceinline__ float fast_sig(float x) {
    return __fdividef(1.0f, 1.0f + __expf(-x));
}
__device__ __forceinline__ float fast_tanh(float x) {
    float s = __fdividef(1.0f, 1.0f + __expf(-2.0f * x));
    return fmaf(2.0f, s, -1.0f);
}

// ---------------------------------------------------------------------------
// prep: v = W_ih@w_enc, u = W_ih@b_enc + b_ih + b_hh; transpose W_hh into
// g_Wt4 (coalesced-by-row layout). One thread per global gate row (3072).
// ---------------------------------------------------------------------------
__global__ void prep_kernel(const float* __restrict__ W_ih,
                            const float* __restrict__ W_enc,
                            const float* __restrict__ b_enc,
                            const float* __restrict__ b_ih,
                            const float* __restrict__ b_hh,
                            const float* __restrict__ W_hh) {
    __shared__ float we[H_];
    __shared__ float be[H_];
    int tid = threadIdx.x;
    we[tid] = W_enc[tid];
    be[tid] = b_enc[tid];
    __syncthreads();

    int r   = blockIdx.x * 256 + tid;   // 0..3071
    int l   = r >> 10;
    int row = r & 1023;
    const float4* Wr = reinterpret_cast<const float4*>(W_ih + (size_t)r * H_);
    const float4* Hr = reinterpret_cast<const float4*>(W_hh + (size_t)r * H_);
    float4* dst = g_Wt4 + (((size_t)l) << 16) + row;

    float sv = 0.f, su = 0.f;
#pragma unroll 4
    for (int k4 = 0; k4 < 64; k4++) {
        float4 w = __ldg(Wr + k4);
        int k = 4 * k4;
        sv = fmaf(w.x, we[k + 0], sv); sv = fmaf(w.y, we[k + 1], sv);
        sv = fmaf(w.z, we[k + 2], sv); sv = fmaf(w.w, we[k + 3], sv);
        su = fmaf(w.x, be[k + 0], su); su = fmaf(w.y, be[k + 1], su);
        su = fmaf(w.z, be[k + 2], su); su = fmaf(w.w, be[k + 3], su);
        dst[k4 << 10] = __ldg(Hr + k4);
    }
    g_v[r] = sv;
    g_u[r] = su + b_ih[r] + b_hh[r];
}

// ---------------------------------------------------------------------------
// order: rank jobs by descending trunk length (LPT) + ticket reset.
// ---------------------------------------------------------------------------
__global__ void order_kernel(const int* __restrict__ trunk_len) {
    __shared__ int len_s[NJOBS];
    int i = threadIdx.x;               // 0..383
    int l = i >> 7;
    int t = (i >> 2) & 31;
    int L = trunk_len[l * NT + t];
    L = min(max(L, 1), TL);
    len_s[i] = L;
    __syncthreads();
    int Li = len_s[i];
    int rank = 0;
    for (int k = 0; k < NJOBS; k++) {
        int Lk = len_s[k];
        rank += (Lk > Li) || (Lk == Li && k < i);
    }
    g_order[rank] = i;
    if (i == 0) g_ticket = 0;
}

// ---------------------------------------------------------------------------
// Main LSTM: 512-thread persistent CTAs, LPT ticket dispatch.
// GATE-SPLIT mapping: thread (j = tid&255, hh = tid>>8) owns gate rows
// {2hh*256+j, (2hh+1)*256+j} for ALL 16 batch rows (8 f32x2 batch pairs).
// Every W row is read by exactly ONE thread (no duplicate stream, no L1
// dependence, no re-convergence barriers). Gate halves are exchanged through
// shared memory before activations (2 barriers/step total).
// ---------------------------------------------------------------------------
__global__ void __launch_bounds__(512, 1)
lstm_kernel(const float* __restrict__ bf,
            const int*   __restrict__ trunk_idx,
            const int*   __restrict__ trunk_len,
            const float* __restrict__ W_lin) {
    extern __shared__ char smem[];
    float2* hp   = reinterpret_cast<float2*>(smem + SM_HP);   // [8][256] pair p = rows 2p,2p+1
    float2* sbf2 = reinterpret_cast<float2*>(smem + SM_SBF);  // [8][128]
    float2* ex   = reinterpret_cast<float2*>(smem + SM_EX);   // [writer][g][pl][256]
    int*    idx_s = reinterpret_cast<int*>(smem + SM_IDX);
    int*    misc  = reinterpret_cast<int*>(smem + SM_MISC);

    const int tid = threadIdx.x;
    const int j   = tid & 255;
    const int hh  = tid >> 8;          // gate half: gates {2hh, 2hh+1}

    for (;;) {
        if (tid == 0) {
            int tk = atomicAdd(&g_ticket, 1);
            misc[0] = (tk < NJOBS) ? g_order[tk] : -1;
        }
        __syncthreads();
        const int job = misc[0];
        if (job < 0) break;

        const int l  = job >> 7;
        const int t  = (job >> 2) & 31;
        const int bc = job & 3;

        // This thread's two gates: global gate index 2hh+g, row (2hh+g)*256+j.
        float vj[2], uj[2];
#pragma unroll
        for (int g = 0; g < 2; g++) {
            int row = (2 * hh + g) * 256 + j;
            vj[g] = g_v[l * 1024 + row];
            uj[g] = g_u[l * 1024 + row];
        }
        for (int i = tid; i < 8 * N_; i += 512) {
            int p = i >> 7, n = i & 127;
            int row0 = bc * MB + 2 * p;
            sbf2[p * N_ + n] = make_float2(bf[row0 * N_ + n], bf[(row0 + 1) * N_ + n]);
        }
        if (tid < TL) idx_s[tid] = trunk_idx[(l * NT + t) * TL + tid];
        if (tid == 0) {
            int L = trunk_len[l * NT + t];
            misc[1] = min(max(L, 1), TL);
        }
        for (int i = tid; i < 8 * H_; i += 512)
            hp[i] = make_float2(0.f, 0.f);
        __syncthreads();

        const int len = misc[1];
        // c for this thread's activation rows: m = 8hh + [0,8)
        float c[8];
#pragma unroll
        for (int m = 0; m < 8; m++) c[m] = 0.f;

        // W rows: (2hh)*256+j and (2hh+1)*256+j, at g_Wt4[l][k4][row]
        const float4* Wk = g_Wt4 + (((size_t)l) << 16) + (hh << 9) + j;

        for (int step = 0; step < len; step++) {
            const int n = idx_s[step];

            // acc[g][p]: f32x2 = gate (2hh+g) values for batch rows (2p, 2p+1)
            unsigned long long acc[2][8];
#pragma unroll
            for (int p = 0; p < 8; p++) {
                float2 s2 = sbf2[p * N_ + n];
#pragma unroll
                for (int g = 0; g < 2; g++)
                    acc[g][p] = pack2(fmaf(s2.x, vj[g], uj[g]),
                                      fmaf(s2.y, vj[g], uj[g]));
            }

            // Recurrent GEMM: no duplicate W reads -> no re-conv barriers.
#pragma unroll 2
            for (int k4 = 0; k4 < 64; k4++) {
                const float4 w0 = __ldg(Wk + (k4 << 10));          // gate 2hh
                const float4 w1 = __ldg(Wk + (k4 << 10) + 256);    // gate 2hh+1
                unsigned long long wp00 = pack2(w0.x, w0.x);
                unsigned long long wp01 = pack2(w0.y, w0.y);
                unsigned long long wp02 = pack2(w0.z, w0.z);
                unsigned long long wp03 = pack2(w0.w, w0.w);
                unsigned long long wp10 = pack2(w1.x, w1.x);
                unsigned long long wp11 = pack2(w1.y, w1.y);
                unsigned long long wp12 = pack2(w1.z, w1.z);
                unsigned long long wp13 = pack2(w1.w, w1.w);
#pragma unroll
                for (int p = 0; p < 8; p++) {
                    const ulonglong2 qa = *reinterpret_cast<const ulonglong2*>(
                        &hp[p * H_ + k4 * 4]);
                    const ulonglong2 qb = *reinterpret_cast<const ulonglong2*>(
                        &hp[p * H_ + k4 * 4 + 2]);
                    acc[0][p] = ffma2(qa.x, wp00, acc[0][p]);
                    acc[0][p] = ffma2(qa.y, wp01, acc[0][p]);
                    acc[0][p] = ffma2(qb.x, wp02, acc[0][p]);
                    acc[0][p] = ffma2(qb.y, wp03, acc[0][p]);
                    acc[1][p] = ffma2(qa.x, wp10, acc[1][p]);
                    acc[1][p] = ffma2(qa.y, wp11, acc[1][p]);
                    acc[1][p] = ffma2(qb.x, wp12, acc[1][p]);
                    acc[1][p] = ffma2(qb.y, wp13, acc[1][p]);
                }
            }

            // Exchange: each half stores the gate values the OTHER half
            // activates. hh=0 activates pairs 0..3, hh=1 activates pairs 4..7.
#pragma unroll
            for (int g = 0; g < 2; g++)
#pragma unroll
                for (int pl = 0; pl < 4; pl++) {
                    int psrc = hh ? pl : 4 + pl;   // pairs the other half needs
                    float lo, hi;
                    unpack2(acc[g][psrc], lo, hi);
                    ex[(((hh * 2 + g) * 4) + pl) * 256 + j] = make_float2(lo, hi);
                }
            __syncthreads();   // exch visible; all GEMM hp reads complete

            // Activations for own rows m = 8hh + [0,8)  (pairs 4hh + [0,4))
#pragma unroll
            for (int pl = 0; pl < 4; pl++) {
                float i0, i1, f0, f1, g0, g1, o0, o1;
                if (hh == 0) {
                    unpack2(acc[0][pl], i0, i1);    // own: gate i
                    unpack2(acc[1][pl], f0, f1);    // own: gate f
                    float2 g2 = ex[((2 * 2 + 0) * 4 + pl - 4 * 2 + 8) * 256 + j];
                    // writer=1, g=0 -> index ((1*2+0)*4+pl)
                    g2 = ex[((1 * 2 + 0) * 4 + pl) * 256 + j];
                    float2 o2 = ex[((1 * 2 + 1) * 4 + pl) * 256 + j];
                    g0 = g2.x; g1 = g2.y; o0 = o2.x; o1 = o2.y;
                } else {
                    float2 i2 = ex[((0 * 2 + 0) * 4 + pl) * 256 + j];
                    float2 f2 = ex[((0 * 2 + 1) * 4 + pl) * 256 + j];
                    i0 = i2.x; i1 = i2.y; f0 = f2.x; f1 = f2.y;
                    unpack2(acc[0][4 + pl], g0, g1);  // own: gate g
                    unpack2(acc[1][4 + pl], o0, o1);  // own: gate o
                }
                float c0 = fmaf(fast_sig(f0), c[2 * pl],     fast_sig(i0) * fast_tanh(g0));
                float c1 = fmaf(fast_sig(f1), c[2 * pl + 1], fast_sig(i1) * fast_tanh(g1));
                c[2 * pl] = c0; c[2 * pl + 1] = c1;
                hp[(4 * hh + pl) * H_ + j] =
                    make_float2(fast_sig(o0) * fast_tanh(c0),
                                fast_sig(o1) * fast_tanh(c1));
            }
            __syncthreads();   // hp ready for next step
        }

        // ---- epilogue: partial[m][o] = h_last[m] @ W_lin[l][:,o] ----
        if (hh == 0 && j < MB * OUT_) {
            int m = j / OUT_;
            int o = j - m * OUT_;
            int p = m >> 1;
            int hi = m & 1;
            const float* Wl = W_lin + (size_t)l * H_ * OUT_ + o;
            float s = 0.f;
#pragma unroll 8
            for (int d = 0; d < H_; d++) {
                float2 hv2 = hp[p * H_ + d];
                s = fmaf(hi ? hv2.y : hv2.x, __ldg(Wl + d * OUT_), s);
            }
            g_partial[(job * MB + m) * OUT_ + o] = s;
        }
        __syncthreads();   // protect shared state before next job
    }
}

// ---------------------------------------------------------------------------
// Deterministic final reduction over trunks and levels (+ b_lin per level).
// ---------------------------------------------------------------------------
__global__ void reduce_kernel(const float* __restrict__ b_lin,
                              float* __restrict__ out) {
    int i = blockIdx.x * blockDim.x + threadIdx.x;
    if (i >= B_ * OUT_) return;
    int b  = i / OUT_;
    int o  = i % OUT_;
    int bc = b / MB;
    int m  = b % MB;
    float s = 0.f;
#pragma unroll
    for (int l = 0; l < LVLS; l++) {
        s += b_lin[l * OUT_ + o];
        for (int t = 0; t < NT; t++) {
            int job = (l * NT + t) * BC + bc;
            s += g_partial[(job * MB + m) * OUT_ + o];
        }
    }
    out[i] = s;
}

// ---------------------------------------------------------------------------
extern "C" void kernel_launch(void* const* d_in, const int* in_sizes, int n_in,
                              void* d_out, int out_size) {
    const float* batch_feature = (const float*)d_in[0];
    const int*   trunk_idx     = (const int*)  d_in[1];
    const int*   trunk_len     = (const int*)  d_in[2];
    const float* W_enc         = (const float*)d_in[3];
    const float* b_enc         = (const float*)d_in[4];
    const float* W_ih          = (const float*)d_in[5];
    const float* W_hh          = (const float*)d_in[6];
    const float* b_ih          = (const float*)d_in[7];
    const float* b_hh          = (const float*)d_in[8];
    const float* W_lin         = (const float*)d_in[9];
    const float* b_lin         = (const float*)d_in[10];
    float* out = (float*)d_out;

    cudaFuncSetAttribute(lstm_kernel,
                         cudaFuncAttributeMaxDynamicSharedMemorySize, SM_SZ);

    prep_kernel<<<12, 256>>>(W_ih, W_enc, b_enc, b_ih, b_hh, W_hh);
    order_kernel<<<1, NJOBS>>>(trunk_len);
    lstm_kernel<<<NJOBS, 512, SM_SZ>>>(batch_feature, trunk_idx, trunk_len, W_lin);
    reduce_kernel<<<(B_ * OUT_ + 127) / 128, 128>>>(b_lin, out);
}

// round 12
// speedup vs baseline: 1.3489x; 1.0018x over previous
#include <cuda_runtime.h>
#include <cuda_bf16.h>
#include <cstdint>

// Problem constants
#define B_    64
#define N_    128
#define LVLS  3
#define NT    32
#define TL    32
#define H_    256
#define OUT_  10
#define BC    4              // batch chunks
#define MB    16             // batch rows per chunk
#define NJOBS (LVLS*NT*BC)   // 384

// Dynamic smem layout (bytes)
#define SM_HP   0                         // float2 hp[8][256]   = 16384
#define SM_SBF  16384                     // float2 sbf2[8][128] =  8192
#define SM_EX   24576                     // float2 ex[2][2][4][256] = 32768
#define SM_IDX  57344                     // int idx_s[TL]
#define SM_MISC 57472                     // int misc[2] : job, len
#define SM_SZ   57600

// Device-global scratch (allocation-free)
__device__ float  g_v[LVLS * 1024];
__device__ float  g_u[LVLS * 1024];
__device__ float4 g_Wt4[LVLS * 64 * 1024];   // [l][k4][row] = W_hh[l][row][4k4..+3]
__device__ float  g_partial[NJOBS * MB * OUT_];
__device__ int    g_order[NJOBS];
__device__ int    g_ticket;

// ---- packed f32x2 helpers (sm_100+) --------------------------------------
__device__ __forceinline__ unsigned long long pack2(float lo, float hi) {
    unsigned long long r;
    asm("mov.b64 %0, {%1, %2};" : "=l"(r) : "f"(lo), "f"(hi));
    return r;
}
__device__ __forceinline__ void unpack2(unsigned long long v, float& lo, float& hi) {
    asm("mov.b64 {%0, %1}, %2;" : "=f"(lo), "=f"(hi) : "l"(v));
}
__device__ __forceinline__ unsigned long long ffma2(unsigned long long a,
                                                    unsigned long long b,
                                                    unsigned long long c) {
    unsigned long long d;
    asm("fma.rn.f32x2 %0, %1, %2, %3;" : "=l"(d) : "l"(a), "l"(b), "l"(c));
    return d;
}

__device__ __forceinline__ float fast_sig(float x) {
    return __fdividef(1.0f, 1.0f + __expf(-x));
}
__device__ __forceinline__ float fast_tanh(float x) {
    float s = __fdividef(1.0f, 1.0f + __expf(-2.0f * x));
    return fmaf(2.0f, s, -1.0f);
}

// ---------------------------------------------------------------------------
// prep: v = W_ih@w_enc, u = W_ih@b_enc + b_ih + b_hh; transpose W_hh into
// g_Wt4 (coalesced-by-row layout). One thread per global gate row (3072).
// ---------------------------------------------------------------------------
__global__ void prep_kernel(const float* __restrict__ W_ih,
                            const float* __restrict__ W_enc,
                            const float* __restrict__ b_enc,
                            const float* __restrict__ b_ih,
                            const float* __restrict__ b_hh,
                            const float* __restrict__ W_hh) {
    __shared__ float we[H_];
    __shared__ float be[H_];
    int tid = threadIdx.x;
    we[tid] = W_enc[tid];
    be[tid] = b_enc[tid];
    __syncthreads();

    int r   = blockIdx.x * 256 + tid;   // 0..3071
    int l   = r >> 10;
    int row = r & 1023;
    const float4* Wr = reinterpret_cast<const float4*>(W_ih + (size_t)r * H_);
    const float4* Hr = reinterpret_cast<const float4*>(W_hh + (size_t)r * H_);
    float4* dst = g_Wt4 + (((size_t)l) << 16) + row;

    float sv = 0.f, su = 0.f;
#pragma unroll 4
    for (int k4 = 0; k4 < 64; k4++) {
        float4 w = __ldg(Wr + k4);
        int k = 4 * k4;
        sv = fmaf(w.x, we[k + 0], sv); sv = fmaf(w.y, we[k + 1], sv);
        sv = fmaf(w.z, we[k + 2], sv); sv = fmaf(w.w, we[k + 3], sv);
        su = fmaf(w.x, be[k + 0], su); su = fmaf(w.y, be[k + 1], su);
        su = fmaf(w.z, be[k + 2], su); su = fmaf(w.w, be[k + 3], su);
        dst[k4 << 10] = __ldg(Hr + k4);
    }
    g_v[r] = sv;
    g_u[r] = su + b_ih[r] + b_hh[r];
}

// ---------------------------------------------------------------------------
// order: rank jobs by descending trunk length (LPT) + ticket reset.
// ---------------------------------------------------------------------------
__global__ void order_kernel(const int* __restrict__ trunk_len) {
    __shared__ int len_s[NJOBS];
    int i = threadIdx.x;               // 0..383
    int l = i >> 7;
    int t = (i >> 2) & 31;
    int L = trunk_len[l * NT + t];
    L = min(max(L, 1), TL);
    len_s[i] = L;
    __syncthreads();
    int Li = len_s[i];
    int rank = 0;
    for (int k = 0; k < NJOBS; k++) {
        int Lk = len_s[k];
        rank += (Lk > Li) || (Lk == Li && k < i);
    }
    g_order[rank] = i;
    if (i == 0) g_ticket = 0;
}

// ---------------------------------------------------------------------------
// Main LSTM: 512-thread persistent CTAs, LPT ticket dispatch.
// GATE-SPLIT mapping: thread (j = tid&255, hh = tid>>8) owns gate rows
// {2hh*256+j, (2hh+1)*256+j} for ALL 16 batch rows (8 f32x2 batch pairs).
// Every W row is read by exactly ONE thread (no duplicate stream, no L1
// dependence, no re-convergence barriers). Gate halves are exchanged through
// shared memory before activations (2 barriers/step total).
// ---------------------------------------------------------------------------
__global__ void __launch_bounds__(512, 1)
lstm_kernel(const float* __restrict__ bf,
            const int*   __restrict__ trunk_idx,
            const int*   __restrict__ trunk_len,
            const float* __restrict__ W_lin) {
    extern __shared__ char smem[];
    float2* hp   = reinterpret_cast<float2*>(smem + SM_HP);   // [8][256] pair p = rows 2p,2p+1
    float2* sbf2 = reinterpret_cast<float2*>(smem + SM_SBF);  // [8][128]
    float2* ex   = reinterpret_cast<float2*>(smem + SM_EX);   // [writer][g][pl][256]
    int*    idx_s = reinterpret_cast<int*>(smem + SM_IDX);
    int*    misc  = reinterpret_cast<int*>(smem + SM_MISC);

    const int tid = threadIdx.x;
    const int j   = tid & 255;
    const int hh  = tid >> 8;          // gate half: gates {2hh, 2hh+1}

    for (;;) {
        if (tid == 0) {
            int tk = atomicAdd(&g_ticket, 1);
            misc[0] = (tk < NJOBS) ? g_order[tk] : -1;
        }
        __syncthreads();
        const int job = misc[0];
        if (job < 0) break;

        const int l  = job >> 7;
        const int t  = (job >> 2) & 31;
        const int bc = job & 3;

        // This thread's two gates: global gate index 2hh+g, row (2hh+g)*256+j.
        float vj[2], uj[2];
#pragma unroll
        for (int g = 0; g < 2; g++) {
            int row = (2 * hh + g) * 256 + j;
            vj[g] = g_v[l * 1024 + row];
            uj[g] = g_u[l * 1024 + row];
        }
        for (int i = tid; i < 8 * N_; i += 512) {
            int p = i >> 7, n = i & 127;
            int row0 = bc * MB + 2 * p;
            sbf2[p * N_ + n] = make_float2(bf[row0 * N_ + n], bf[(row0 + 1) * N_ + n]);
        }
        if (tid < TL) idx_s[tid] = trunk_idx[(l * NT + t) * TL + tid];
        if (tid == 0) {
            int L = trunk_len[l * NT + t];
            misc[1] = min(max(L, 1), TL);
        }
        for (int i = tid; i < 8 * H_; i += 512)
            hp[i] = make_float2(0.f, 0.f);
        __syncthreads();

        const int len = misc[1];
        // c for this thread's activation rows: m = 8hh + [0,8)
        float c[8];
#pragma unroll
        for (int m = 0; m < 8; m++) c[m] = 0.f;

        // W rows: (2hh)*256+j and (2hh+1)*256+j, at g_Wt4[l][k4][row]
        const float4* Wk = g_Wt4 + (((size_t)l) << 16) + (hh << 9) + j;

        for (int step = 0; step < len; step++) {
            const int n = idx_s[step];

            // acc[g][p]: f32x2 = gate (2hh+g) values for batch rows (2p, 2p+1)
            unsigned long long acc[2][8];
#pragma unroll
            for (int p = 0; p < 8; p++) {
                float2 s2 = sbf2[p * N_ + n];
#pragma unroll
                for (int g = 0; g < 2; g++)
                    acc[g][p] = pack2(fmaf(s2.x, vj[g], uj[g]),
                                      fmaf(s2.y, vj[g], uj[g]));
            }

            // Recurrent GEMM: no duplicate W reads -> no re-conv barriers.
#pragma unroll 2
            for (int k4 = 0; k4 < 64; k4++) {
                const float4 w0 = __ldg(Wk + (k4 << 10));          // gate 2hh
                const float4 w1 = __ldg(Wk + (k4 << 10) + 256);    // gate 2hh+1
                unsigned long long wp00 = pack2(w0.x, w0.x);
                unsigned long long wp01 = pack2(w0.y, w0.y);
                unsigned long long wp02 = pack2(w0.z, w0.z);
                unsigned long long wp03 = pack2(w0.w, w0.w);
                unsigned long long wp10 = pack2(w1.x, w1.x);
                unsigned long long wp11 = pack2(w1.y, w1.y);
                unsigned long long wp12 = pack2(w1.z, w1.z);
                unsigned long long wp13 = pack2(w1.w, w1.w);
#pragma unroll
                for (int p = 0; p < 8; p++) {
                    const ulonglong2 qa = *reinterpret_cast<const ulonglong2*>(
                        &hp[p * H_ + k4 * 4]);
                    const ulonglong2 qb = *reinterpret_cast<const ulonglong2*>(
                        &hp[p * H_ + k4 * 4 + 2]);
                    acc[0][p] = ffma2(qa.x, wp00, acc[0][p]);
                    acc[0][p] = ffma2(qa.y, wp01, acc[0][p]);
                    acc[0][p] = ffma2(qb.x, wp02, acc[0][p]);
                    acc[0][p] = ffma2(qb.y, wp03, acc[0][p]);
                    acc[1][p] = ffma2(qa.x, wp10, acc[1][p]);
                    acc[1][p] = ffma2(qa.y, wp11, acc[1][p]);
                    acc[1][p] = ffma2(qb.x, wp12, acc[1][p]);
                    acc[1][p] = ffma2(qb.y, wp13, acc[1][p]);
                }
            }

            // Exchange: each half stores the gate values the OTHER half
            // activates. hh=0 activates pairs 0..3, hh=1 activates pairs 4..7.
#pragma unroll
            for (int g = 0; g < 2; g++)
#pragma unroll
                for (int pl = 0; pl < 4; pl++) {
                    int psrc = hh ? pl : 4 + pl;   // pairs the other half needs
                    float lo, hi;
                    unpack2(acc[g][psrc], lo, hi);
                    ex[(((hh * 2 + g) * 4) + pl) * 256 + j] = make_float2(lo, hi);
                }
            __syncthreads();   // exch visible; all GEMM hp reads complete

            // Activations for own rows m = 8hh + [0,8)  (pairs 4hh + [0,4))
#pragma unroll
            for (int pl = 0; pl < 4; pl++) {
                float i0, i1, f0, f1, g0, g1, o0, o1;
                if (hh == 0) {
                    unpack2(acc[0][pl], i0, i1);    // own: gate i
                    unpack2(acc[1][pl], f0, f1);    // own: gate f
                    float2 g2 = ex[((2 * 2 + 0) * 4 + pl - 4 * 2 + 8) * 256 + j];
                    // writer=1, g=0 -> index ((1*2+0)*4+pl)
                    g2 = ex[((1 * 2 + 0) * 4 + pl) * 256 + j];
                    float2 o2 = ex[((1 * 2 + 1) * 4 + pl) * 256 + j];
                    g0 = g2.x; g1 = g2.y; o0 = o2.x; o1 = o2.y;
                } else {
                    float2 i2 = ex[((0 * 2 + 0) * 4 + pl) * 256 + j];
                    float2 f2 = ex[((0 * 2 + 1) * 4 + pl) * 256 + j];
                    i0 = i2.x; i1 = i2.y; f0 = f2.x; f1 = f2.y;
                    unpack2(acc[0][4 + pl], g0, g1);  // own: gate g
                    unpack2(acc[1][4 + pl], o0, o1);  // own: gate o
                }
                float c0 = fmaf(fast_sig(f0), c[2 * pl],     fast_sig(i0) * fast_tanh(g0));
                float c1 = fmaf(fast_sig(f1), c[2 * pl + 1], fast_sig(i1) * fast_tanh(g1));
                c[2 * pl] = c0; c[2 * pl + 1] = c1;
                hp[(4 * hh + pl) * H_ + j] =
                    make_float2(fast_sig(o0) * fast_tanh(c0),
                                fast_sig(o1) * fast_tanh(c1));
            }
            __syncthreads();   // hp ready for next step
        }

        // ---- epilogue: partial[m][o] = h_last[m] @ W_lin[l][:,o] ----
        if (hh == 0 && j < MB * OUT_) {
            int m = j / OUT_;
            int o = j - m * OUT_;
            int p = m >> 1;
            int hi = m & 1;
            const float* Wl = W_lin + (size_t)l * H_ * OUT_ + o;
            float s = 0.f;
#pragma unroll 8
            for (int d = 0; d < H_; d++) {
                float2 hv2 = hp[p * H_ + d];
                s = fmaf(hi ? hv2.y : hv2.x, __ldg(Wl + d * OUT_), s);
            }
            g_partial[(job * MB + m) * OUT_ + o] = s;
        }
        __syncthreads();   // protect shared state before next job
    }
}

// ---------------------------------------------------------------------------
// Deterministic final reduction over trunks and levels (+ b_lin per level).
// ---------------------------------------------------------------------------
__global__ void reduce_kernel(const float* __restrict__ b_lin,
                              float* __restrict__ out) {
    int i = blockIdx.x * blockDim.x + threadIdx.x;
    if (i >= B_ * OUT_) return;
    int b  = i / OUT_;
    int o  = i % OUT_;
    int bc = b / MB;
    int m  = b % MB;
    float s = 0.f;
#pragma unroll
    for (int l = 0; l < LVLS; l++) {
        s += b_lin[l * OUT_ + o];
        for (int t = 0; t < NT; t++) {
            int job = (l * NT + t) * BC + bc;
            s += g_partial[(job * MB + m) * OUT_ + o];
        }
    }
    out[i] = s;
}

// ---------------------------------------------------------------------------
extern "C" void kernel_launch(void* const* d_in, const int* in_sizes, int n_in,
                              void* d_out, int out_size) {
    const float* batch_feature = (const float*)d_in[0];
    const int*   trunk_idx     = (const int*)  d_in[1];
    const int*   trunk_len     = (const int*)  d_in[2];
    const float* W_enc         = (const float*)d_in[3];
    const float* b_enc         = (const float*)d_in[4];
    const float* W_ih          = (const float*)d_in[5];
    const float* W_hh          = (const float*)d_in[6];
    const float* b_ih          = (const float*)d_in[7];
    const float* b_hh          = (const float*)d_in[8];
    const float* W_lin         = (const float*)d_in[9];
    const float* b_lin         = (const float*)d_in[10];
    float* out = (float*)d_out;

    cudaFuncSetAttribute(lstm_kernel,
                         cudaFuncAttributeMaxDynamicSharedMemorySize, SM_SZ);

    prep_kernel<<<12, 256>>>(W_ih, W_enc, b_enc, b_ih, b_hh, W_hh);
    order_kernel<<<1, NJOBS>>>(trunk_len);
    lstm_kernel<<<NJOBS, 512, SM_SZ>>>(batch_feature, trunk_idx, trunk_len, W_lin);
    reduce_kernel<<<(B_ * OUT_ + 127) / 128, 128>>>(b_lin, out);
}